// round 5
// baseline (speedup 1.0000x reference)
#include <cuda_runtime.h>

#define HW 4096
#define NM 512

__device__ float  g_c[64], g_s[64];
__device__ float2 g_wmix[6 * NM * 4096];      // [j][m][i*64+o], scaled
__device__ float2 g_specX[NM * 2048];         // [m][bt*64+c]
__device__ float2 g_specB[3 * NM * 2048];     // [jj][m][bt*64+o]
__device__ float2 g_specH[NM * 256];
__device__ float2 g_specF[2 * NM * 256];
__device__ float  g_Ax[3 * 32 * 64 * HW];     // [jj][bt][o][p]
__device__ float  g_Fzr[2 * 256 * HW];
__device__ float  g_F5[256 * HW];
__device__ float  g_z[256 * HW];
__device__ float  g_rh[256 * HW];
__device__ float  g_h[256 * HW];

__global__ void k_twiddle() {
    int n = threadIdx.x;
    float s, c;
    sincospif(n * (1.0f / 32.0f), &s, &c);
    g_c[n] = c; g_s[n] = s;
}

// sw[j][i][o][kx][ky][2] -> g_wmix[j][m][i*64+o], m = kxi*16+ky, scale c_ky/4096
__global__ __launch_bounds__(256) void k_wtrans(const float* __restrict__ sw1,
                                                const float* __restrict__ sw2) {
    int bx = blockIdx.x;
    int j = bx >> 9, i = (bx >> 3) & 63, o0 = (bx & 7) * 8, tid = threadIdx.x;
    __shared__ float t1[4096], t2[4096];
    const float* s1 = sw1 + ((size_t)((j * 64 + i) * 64) + o0) * 512;
    const float* s2 = sw2 + ((size_t)((j * 64 + i) * 64) + o0) * 512;
    for (int idx = tid; idx < 4096; idx += 256) { t1[idx] = s1[idx]; t2[idx] = s2[idx]; }
    __syncthreads();
    float2* dst = g_wmix + (size_t)j * NM * 4096 + i * 64 + o0;
    for (int idx = tid; idx < NM * 8; idx += 256) {
        int m = idx >> 3, oo = idx & 7;
        int kxi = m >> 4, ky = m & 15;
        float f = (ky == 0 ? 1.0f : 2.0f) * (1.0f / 4096.0f);
        const float* tt = (kxi < 16) ? t1 : t2;
        int kk = (kxi < 16) ? kxi : (kxi - 16);
        float re = tt[oo * 512 + kk * 32 + ky * 2];
        float im = tt[oo * 512 + kk * 32 + ky * 2 + 1];
        dst[(size_t)m * 4096 + oo] = make_float2(re * f, im * f);
    }
}

__global__ void k_hinit(const float* __restrict__ bh) {
    float v = bh[0];
    int idx = blockIdx.x * 256 + threadIdx.x;
    #pragma unroll
    for (int k = 0; k < 4; k++) g_h[idx + k * 262144] = v;
}

// partial forward DFT of one 64x64 image -> spec[m][img], m=kxi*16+ky
__global__ __launch_bounds__(256) void k_fwd(const float* __restrict__ in,
                                             float2* __restrict__ spec, int nimg) {
    __shared__ float xs[64 * 65];
    __shared__ float Yre[64 * 17], Yim[64 * 17];
    __shared__ float cs[64], ss[64];
    int tid = threadIdx.x, img = blockIdx.x;
    if (tid < 64) { cs[tid] = g_c[tid]; ss[tid] = g_s[tid]; }
    const float* src = in + (size_t)img * HW;
    for (int idx = tid; idx < HW; idx += 256)
        xs[(idx >> 6) * 65 + (idx & 63)] = src[idx];
    __syncthreads();
    {   // y -> ky (16 modes); thread: one x row, 4 ky
        int x = tid >> 2, kq = tid & 3;
        const float* row = xs + x * 65;
        float ar[4] = {0,0,0,0}, ai[4] = {0,0,0,0};
        int ii[4] = {0,0,0,0};
        #pragma unroll 8
        for (int y = 0; y < 64; y++) {
            float v = row[y];
            #pragma unroll
            for (int k = 0; k < 4; k++) {
                ar[k] += v * cs[ii[k]];
                ai[k] -= v * ss[ii[k]];
                ii[k] = (ii[k] + kq * 4 + k) & 63;
            }
        }
        #pragma unroll
        for (int k = 0; k < 4; k++) { Yre[x*17 + kq*4+k] = ar[k]; Yim[x*17 + kq*4+k] = ai[k]; }
    }
    __syncthreads();
    {   // x -> kx (rows 0..15 and 48..63)
        int ky = tid & 15, kg = tid >> 4;
        float z0r=0, z0i=0, z1r=0, z1i=0;
        int i0 = 0, i1 = 0;
        #pragma unroll 8
        for (int x = 0; x < 64; x++) {
            float yr = Yre[x*17 + ky], yi = Yim[x*17 + ky];
            float c = cs[i0], s = ss[i0];
            z0r += yr*c + yi*s; z0i += yi*c - yr*s;
            c = cs[i1]; s = ss[i1];
            z1r += yr*c + yi*s; z1i += yi*c - yr*s;
            i0 = (i0 + kg) & 63; i1 = (i1 + kg + 48) & 63;
        }
        spec[(size_t)(kg * 16 + ky) * nimg + img]        = make_float2(z0r, z0i);
        spec[(size_t)((kg + 16) * 16 + ky) * nimg + img] = make_float2(z1r, z1i);
    }
}

// mode mix for the 32-image precompute: specB[jj][m][*] = specX[m][*] x W(2*jj)
__global__ __launch_bounds__(256) void k_mix32() {
    int m = blockIdx.x, jj = blockIdx.y, tid = threadIdx.x;
    const float2* W = g_wmix + ((size_t)(2 * jj) * NM + m) * 4096;
    __shared__ float2 ins[2048];
    __shared__ float2 ws[4096];
    for (int idx = tid; idx < 2048; idx += 256) ins[idx] = g_specX[(size_t)m * 2048 + idx];
    for (int idx = tid; idx < 4096; idx += 256) ws[idx] = W[idx];
    __syncthreads();
    int o = tid & 63, bq = tid >> 6;
    float2 acc[8];
    #pragma unroll
    for (int g = 0; g < 8; g++) acc[g] = make_float2(0.f, 0.f);
    for (int i = 0; i < 64; i++) {
        float2 wv = ws[i * 64 + o];
        #pragma unroll
        for (int g = 0; g < 8; g++) {
            float2 iv = ins[(g * 4 + bq) * 64 + i];
            acc[g].x += iv.x * wv.x - iv.y * wv.y;
            acc[g].y += iv.x * wv.y + iv.y * wv.x;
        }
    }
    float2* outp = g_specB + (size_t)jj * NM * 2048 + (size_t)m * 2048;
    #pragma unroll
    for (int g = 0; g < 8; g++) outp[(g * 4 + bq) * 64 + o] = acc[g];
}

// mode mix for 4 images (in-loop), weight wa for jj=0, wb for jj=1
__global__ __launch_bounds__(256) void k_mix4(const float2* __restrict__ inSpec,
                                              float2* __restrict__ outSpec,
                                              int wa, int wb) {
    int m = blockIdx.x, jj = blockIdx.y, tid = threadIdx.x;
    int w = jj ? wb : wa;
    const float2* W = g_wmix + ((size_t)w * NM + m) * 4096;
    __shared__ float2 ins[256];
    ins[tid] = inSpec[(size_t)m * 256 + tid];
    __syncthreads();
    int o = tid & 63, b = tid >> 6;
    float2 acc = make_float2(0.f, 0.f);
    #pragma unroll 8
    for (int i = 0; i < 64; i++) {
        float2 wv = __ldg(&W[i * 64 + o]);
        float2 iv = ins[b * 64 + i];
        acc.x += iv.x * wv.x - iv.y * wv.y;
        acc.y += iv.x * wv.y + iv.y * wv.x;
    }
    outSpec[(size_t)jj * NM * 256 + (size_t)m * 256 + tid] = acc;
}

// partial inverse DFT; optional accumulate into out, optional +Ax[axSel+jj][b*8+t]
__global__ __launch_bounds__(256) void k_inv(const float2* __restrict__ specBase,
                                             int specStride, int nimg,
                                             float* __restrict__ outBase, int outStride,
                                             int accum, int axSel, int t) {
    int img = blockIdx.x, jj = blockIdx.y, tid = threadIdx.x;
    const float2* spec = specBase + (size_t)jj * specStride;
    __shared__ float Zr[512], Zi[512];
    __shared__ __align__(16) float Gr[16 * 68];
    __shared__ __align__(16) float Gi[16 * 68];
    __shared__ float cs[64], ss[64];
    if (tid < 64) { cs[tid] = g_c[tid]; ss[tid] = g_s[tid]; }
    for (int idx = tid; idx < 512; idx += 256) {
        float2 v = spec[(size_t)idx * nimg + img];
        Zr[idx] = v.x; Zi[idx] = v.y;
    }
    __syncthreads();
    {   // kx -> x (e^{+i})
        int ky = tid & 15, xg = tid >> 4, x0 = xg * 4;
        float gr[4] = {0,0,0,0}, gi[4] = {0,0,0,0};
        #pragma unroll 4
        for (int kxi = 0; kxi < 32; kxi++) {
            int kx = kxi + ((kxi >= 16) ? 32 : 0);
            float zr = Zr[kxi * 16 + ky], zi = Zi[kxi * 16 + ky];
            #pragma unroll
            for (int k = 0; k < 4; k++) {
                int id = (kx * (x0 + k)) & 63;
                float c = cs[id], s = ss[id];
                gr[k] += zr * c - zi * s;
                gi[k] += zr * s + zi * c;
            }
        }
        #pragma unroll
        for (int k = 0; k < 4; k++) { Gr[ky*68 + x0+k] = gr[k]; Gi[ky*68 + x0+k] = gi[k]; }
    }
    __syncthreads();
    {   // ky -> y, real part (c_ky folded into weights)
        int y = tid & 63, xq = tid >> 6;
        float acc[16];
        #pragma unroll
        for (int q = 0; q < 16; q++) acc[q] = 0.f;
        for (int ky = 0; ky < 16; ky++) {
            int id = (ky * y) & 63;
            float c = cs[id], s = ss[id];
            const float4* a4 = (const float4*)(Gr + ky * 68 + xq * 16);
            const float4* b4 = (const float4*)(Gi + ky * 68 + xq * 16);
            #pragma unroll
            for (int q = 0; q < 4; q++) {
                float4 a = a4[q], b = b4[q];
                acc[q*4+0] += a.x * c - b.x * s;
                acc[q*4+1] += a.y * c - b.y * s;
                acc[q*4+2] += a.z * c - b.z * s;
                acc[q*4+3] += a.w * c - b.w * s;
            }
        }
        float* outp = outBase + (size_t)jj * outStride + (size_t)img * HW;
        const float* axp = 0;
        if (axSel >= 0) {
            int b = img >> 6, o = img & 63;
            axp = g_Ax + ((size_t)((axSel + jj) * 32 + b * 8 + t) * 64 + o) * HW;
        }
        #pragma unroll
        for (int q = 0; q < 16; q++) {
            int off = (xq * 16 + q) * 64 + y;
            float v = acc[q];
            if (accum) v += outp[off];
            if (axp)   v += axp[off];
            outp[off] = v;
        }
    }
}

// Ax[jj][bt][o][p] = sum_i x[bt][i][p] * skw[2jj][i][o]
__global__ __launch_bounds__(256) void k_skipx(const float* __restrict__ x,
                                               const float* __restrict__ skw) {
    int pt = blockIdx.x, bt = blockIdx.y, jj = blockIdx.z, p0 = pt * 64, tid = threadIdx.x;
    __shared__ float xs[4096];
    __shared__ __align__(16) float ws[4096];
    for (int idx = tid; idx < 4096; idx += 256) {
        int c = idx >> 6, p = idx & 63;
        xs[idx] = x[(size_t)(bt * 64 + c) * HW + p0 + p];
        ws[idx] = skw[(2 * jj) * 4096 + idx];
    }
    __syncthreads();
    int p = tid & 63, og = tid >> 6, o0 = og * 16;
    float a[16];
    #pragma unroll
    for (int k = 0; k < 16; k++) a[k] = 0.f;
    const float4* wv = (const float4*)ws;
    for (int i = 0; i < 64; i++) {
        float v = xs[i * 64 + p];
        int base = i * 16 + (o0 >> 2);
        #pragma unroll
        for (int q = 0; q < 4; q++) {
            float4 w4 = wv[base + q];
            a[q*4+0] += v * w4.x; a[q*4+1] += v * w4.y;
            a[q*4+2] += v * w4.z; a[q*4+3] += v * w4.w;
        }
    }
    float* axp = g_Ax + ((size_t)jj * 32 + bt) * 64 * HW;
    #pragma unroll
    for (int k = 0; k < 16; k++)
        axp[(size_t)(o0 + k) * HW + p0 + p] = a[k];
}

// z = sigmoid(Fzr0 + skip(h,skw1) + gb0); r = sigmoid(Fzr1 + skip(h,skw3) + gb1); rh = r*h
__global__ __launch_bounds__(256) void k_gates(const float* __restrict__ skw,
                                               const float* __restrict__ gb) {
    int pt = blockIdx.x, bt = blockIdx.y, p0 = pt * 64, tid = threadIdx.x;
    __shared__ float hs[4096];
    __shared__ __align__(16) float w1s[4096];
    __shared__ __align__(16) float w3s[4096];
    for (int idx = tid; idx < 4096; idx += 256) {
        int c = idx >> 6, p = idx & 63;
        hs[idx]  = g_h[(size_t)(bt * 64 + c) * HW + p0 + p];
        w1s[idx] = skw[1 * 4096 + idx];
        w3s[idx] = skw[3 * 4096 + idx];
    }
    __syncthreads();
    int p = tid & 63, og = tid >> 6, o0 = og * 16;
    float a1[16], a3[16];
    #pragma unroll
    for (int k = 0; k < 16; k++) { a1[k] = 0.f; a3[k] = 0.f; }
    const float4* w1v = (const float4*)w1s;
    const float4* w3v = (const float4*)w3s;
    for (int i = 0; i < 64; i++) {
        float hv = hs[i * 64 + p];
        int base = i * 16 + (o0 >> 2);
        #pragma unroll
        for (int q = 0; q < 4; q++) {
            float4 a = w1v[base + q], b = w3v[base + q];
            a1[q*4+0] += hv * a.x; a1[q*4+1] += hv * a.y;
            a1[q*4+2] += hv * a.z; a1[q*4+3] += hv * a.w;
            a3[q*4+0] += hv * b.x; a3[q*4+1] += hv * b.y;
            a3[q*4+2] += hv * b.z; a3[q*4+3] += hv * b.w;
        }
    }
    float gb0 = gb[0], gb1 = gb[1];
    #pragma unroll
    for (int k = 0; k < 16; k++) {
        int o = o0 + k;
        size_t off = (size_t)(bt * 64 + o) * HW + p0 + p;
        float z = 1.f / (1.f + expf(-(g_Fzr[off] + a1[k] + gb0)));
        float r = 1.f / (1.f + expf(-(g_Fzr[256 * HW + off] + a3[k] + gb1)));
        g_z[off]  = z;
        g_rh[off] = r * hs[o * 64 + p];
    }
}

// hh = selu(F5 + skip(rh,skw5) + gb2); h = (1-z)h + z*hh
__global__ __launch_bounds__(256) void k_hup(const float* __restrict__ skw,
                                             const float* __restrict__ gb) {
    int pt = blockIdx.x, bt = blockIdx.y, p0 = pt * 64, tid = threadIdx.x;
    __shared__ float rs[4096];
    __shared__ __align__(16) float w5s[4096];
    for (int idx = tid; idx < 4096; idx += 256) {
        int c = idx >> 6, p = idx & 63;
        rs[idx]  = g_rh[(size_t)(bt * 64 + c) * HW + p0 + p];
        w5s[idx] = skw[5 * 4096 + idx];
    }
    __syncthreads();
    int p = tid & 63, og = tid >> 6, o0 = og * 16;
    float a5[16];
    #pragma unroll
    for (int k = 0; k < 16; k++) a5[k] = 0.f;
    const float4* wv = (const float4*)w5s;
    for (int i = 0; i < 64; i++) {
        float v = rs[i * 64 + p];
        int base = i * 16 + (o0 >> 2);
        #pragma unroll
        for (int q = 0; q < 4; q++) {
            float4 a = wv[base + q];
            a5[q*4+0] += v * a.x; a5[q*4+1] += v * a.y;
            a5[q*4+2] += v * a.z; a5[q*4+3] += v * a.w;
        }
    }
    float gb2 = gb[2];
    const float SC = 1.0507009873554805f, AL = 1.6732632423543772f;
    #pragma unroll
    for (int k = 0; k < 16; k++) {
        size_t off = (size_t)(bt * 64 + o0 + k) * HW + p0 + p;
        float v = g_F5[off] + a5[k] + gb2;
        float hh = (v > 0.f) ? SC * v : SC * AL * (expf(v) - 1.f);
        float z = g_z[off], h = g_h[off];
        g_h[off] = (1.f - z) * h + z * hh;
    }
}

__global__ void k_copy(float* __restrict__ out) {
    int idx = blockIdx.x * 256 + threadIdx.x;
    out[idx] = g_h[idx];
}

extern "C" void kernel_launch(void* const* d_in, const int* in_sizes, int n_in,
                              void* d_out, int out_size) {
    const float* x   = (const float*)d_in[0];
    const float* sw1 = (const float*)d_in[1];
    const float* sw2 = (const float*)d_in[2];
    const float* skw = (const float*)d_in[3];
    const float* gb  = (const float*)d_in[4];
    const float* bh  = (const float*)d_in[5];
    float* out = (float*)d_out;

    float2 *pSpecX, *pSpecB, *pSpecH, *pSpecF;
    float *pAx, *pFzr, *pF5, *pH, *pRH;
    cudaGetSymbolAddress((void**)&pSpecX, g_specX);
    cudaGetSymbolAddress((void**)&pSpecB, g_specB);
    cudaGetSymbolAddress((void**)&pSpecH, g_specH);
    cudaGetSymbolAddress((void**)&pSpecF, g_specF);
    cudaGetSymbolAddress((void**)&pAx,  g_Ax);
    cudaGetSymbolAddress((void**)&pFzr, g_Fzr);
    cudaGetSymbolAddress((void**)&pF5,  g_F5);
    cudaGetSymbolAddress((void**)&pH,   g_h);
    cudaGetSymbolAddress((void**)&pRH,  g_rh);

    k_twiddle<<<1, 64>>>();
    k_wtrans<<<3072, 256>>>(sw1, sw2);
    k_hinit<<<1024, 256>>>(bh);
    k_skipx<<<dim3(64, 32, 3), 256>>>(x, skw);
    k_fwd<<<2048, 256>>>(x, pSpecX, 2048);
    k_mix32<<<dim3(512, 3), 256>>>();
    k_inv<<<dim3(2048, 3), 256>>>(pSpecB, NM * 2048, 2048, pAx, 32 * 64 * HW, 1, -1, 0);

    for (int t = 0; t < 8; t++) {
        k_fwd<<<256, 256>>>(pH, pSpecH, 256);
        k_mix4<<<dim3(512, 2), 256>>>(pSpecH, pSpecF, 1, 3);
        k_inv<<<dim3(256, 2), 256>>>(pSpecF, NM * 256, 256, pFzr, 256 * HW, 0, 0, t);
        k_gates<<<dim3(64, 4), 256>>>(skw, gb);
        k_fwd<<<256, 256>>>(pRH, pSpecH, 256);
        k_mix4<<<dim3(512, 1), 256>>>(pSpecH, pSpecF, 5, 5);
        k_inv<<<dim3(256, 1), 256>>>(pSpecF, NM * 256, 256, pF5, 256 * HW, 0, 2, t);
        k_hup<<<dim3(64, 4), 256>>>(skw, gb);
    }
    k_copy<<<4096, 256>>>(out);
}

// round 7
// speedup vs baseline: 1.0968x; 1.0968x over previous
#include <cuda_runtime.h>

#define HW 4096
#define NM 512

__device__ float  g_c[64], g_s[64];
__device__ float2 g_wmix[6 * NM * 4096];      // [j][m][i*64+o], scaled c_ky/4096
__device__ float2 g_specX[NM * 2048];         // [m][bt*64+c]
__device__ float2 g_specB[3 * NM * 2048];     // [jj][m][bt*64+o]
__device__ float2 g_specH[NM * 256];
__device__ float2 g_specF[2 * NM * 256];
__device__ float  g_Ax[3 * 32 * 64 * HW];     // [jj][bt][o][p]  (skip(x)+spectral(x))
__device__ float  g_S13[2 * 4 * 64 * HW];     // [w][b][o][p]  h-skips (skw1, skw3)
__device__ float  g_S5[4 * 64 * HW];          // rh-skip (skw5)
__device__ float  g_z[4 * 64 * HW];
__device__ float  g_rh[4 * 64 * HW];
__device__ float  g_h[4 * 64 * HW];

__global__ void k_twiddle() {
    int n = threadIdx.x;
    float s, c;
    sincospif(n * (1.0f / 32.0f), &s, &c);
    g_c[n] = c; g_s[n] = s;
}

// sw[j][i][o][kx][ky][2] -> g_wmix[j][m][i*64+o], m = kxi*16+ky
__global__ __launch_bounds__(256) void k_wtrans(const float* __restrict__ sw1,
                                                const float* __restrict__ sw2) {
    int bx = blockIdx.x;
    int j = bx >> 9, i = (bx >> 3) & 63, o0 = (bx & 7) * 8, tid = threadIdx.x;
    __shared__ float t1[4096], t2[4096];
    const float* s1 = sw1 + ((size_t)((j * 64 + i) * 64) + o0) * 512;
    const float* s2 = sw2 + ((size_t)((j * 64 + i) * 64) + o0) * 512;
    for (int idx = tid; idx < 4096; idx += 256) { t1[idx] = s1[idx]; t2[idx] = s2[idx]; }
    __syncthreads();
    float2* dst = g_wmix + (size_t)j * NM * 4096 + i * 64 + o0;
    for (int idx = tid; idx < NM * 8; idx += 256) {
        int m = idx >> 3, oo = idx & 7;
        int kxi = m >> 4, ky = m & 15;
        float f = (ky == 0 ? 1.0f : 2.0f) * (1.0f / 4096.0f);
        const float* tt = (kxi < 16) ? t1 : t2;
        int kk = (kxi < 16) ? kxi : (kxi - 16);
        float re = tt[oo * 512 + kk * 32 + ky * 2];
        float im = tt[oo * 512 + kk * 32 + ky * 2 + 1];
        dst[(size_t)m * 4096 + oo] = make_float2(re * f, im * f);
    }
}

__global__ void k_hinit(const float* __restrict__ bh) {
    float v = bh[0];
    int idx = blockIdx.x * 256 + threadIdx.x;
    g_h[idx] = v;
}

// partial forward DFT of one 64x64 image -> spec[m][img], m=kxi*16+ky
__global__ __launch_bounds__(256) void k_fwd(const float* __restrict__ in,
                                             float2* __restrict__ spec, int nimg) {
    __shared__ float xs[64 * 65];
    __shared__ float Yre[64 * 17], Yim[64 * 17];
    __shared__ float cs[64], ss[64];
    int tid = threadIdx.x, img = blockIdx.x;
    if (tid < 64) { cs[tid] = g_c[tid]; ss[tid] = g_s[tid]; }
    const float* src = in + (size_t)img * HW;
    for (int idx = tid; idx < HW; idx += 256)
        xs[(idx >> 6) * 65 + (idx & 63)] = src[idx];
    __syncthreads();
    {   // y -> ky (16 modes); thread: one x row, 4 ky
        int x = tid >> 2, kq = tid & 3;
        const float* row = xs + x * 65;
        float ar[4] = {0,0,0,0}, ai[4] = {0,0,0,0};
        int ii[4] = {0,0,0,0};
        #pragma unroll 8
        for (int y = 0; y < 64; y++) {
            float v = row[y];
            #pragma unroll
            for (int k = 0; k < 4; k++) {
                ar[k] += v * cs[ii[k]];
                ai[k] -= v * ss[ii[k]];
                ii[k] = (ii[k] + kq * 4 + k) & 63;
            }
        }
        #pragma unroll
        for (int k = 0; k < 4; k++) { Yre[x*17 + kq*4+k] = ar[k]; Yim[x*17 + kq*4+k] = ai[k]; }
    }
    __syncthreads();
    {   // x -> kx (rows 0..15 and 48..63)
        int ky = tid & 15, kg = tid >> 4;
        float z0r=0, z0i=0, z1r=0, z1i=0;
        int i0 = 0, i1 = 0;
        #pragma unroll 8
        for (int x = 0; x < 64; x++) {
            float yr = Yre[x*17 + ky], yi = Yim[x*17 + ky];
            float c = cs[i0], s = ss[i0];
            z0r += yr*c + yi*s; z0i += yi*c - yr*s;
            c = cs[i1]; s = ss[i1];
            z1r += yr*c + yi*s; z1i += yi*c - yr*s;
            i0 = (i0 + kg) & 63; i1 = (i1 + kg + 48) & 63;
        }
        spec[(size_t)(kg * 16 + ky) * nimg + img]        = make_float2(z0r, z0i);
        spec[(size_t)((kg + 16) * 16 + ky) * nimg + img] = make_float2(z1r, z1i);
    }
}

// mode mix, 32-image precompute: specB[jj][m][*] = specX[m][*] x W(2*jj)
__global__ __launch_bounds__(256) void k_mix32() {
    int m = blockIdx.x, jj = blockIdx.y, tid = threadIdx.x;
    const float2* W = g_wmix + ((size_t)(2 * jj) * NM + m) * 4096;
    __shared__ float2 ins[2048];
    __shared__ float2 ws[4096];
    for (int idx = tid; idx < 2048; idx += 256) ins[idx] = g_specX[(size_t)m * 2048 + idx];
    for (int idx = tid; idx < 4096; idx += 256) ws[idx] = W[idx];
    __syncthreads();
    int o = tid & 63, bq = tid >> 6;
    float2 acc[8];
    #pragma unroll
    for (int g = 0; g < 8; g++) acc[g] = make_float2(0.f, 0.f);
    for (int i = 0; i < 64; i++) {
        float2 wv = ws[i * 64 + o];
        #pragma unroll
        for (int g = 0; g < 8; g++) {
            float2 iv = ins[(g * 4 + bq) * 64 + i];
            acc[g].x += iv.x * wv.x - iv.y * wv.y;
            acc[g].y += iv.x * wv.y + iv.y * wv.x;
        }
    }
    float2* outp = g_specB + (size_t)jj * NM * 2048 + (size_t)m * 2048;
    #pragma unroll
    for (int g = 0; g < 8; g++) outp[(g * 4 + bq) * 64 + o] = acc[g];
}

// mode mix for 4 images (in-loop)
__global__ __launch_bounds__(256) void k_mix4(const float2* __restrict__ inSpec,
                                              float2* __restrict__ outSpec,
                                              int wa, int wb) {
    int m = blockIdx.x, jj = blockIdx.y, tid = threadIdx.x;
    int w = jj ? wb : wa;
    const float2* W = g_wmix + ((size_t)w * NM + m) * 4096;
    __shared__ float2 ins[256];
    ins[tid] = inSpec[(size_t)m * 256 + tid];
    __syncthreads();
    int o = tid & 63, b = tid >> 6;
    float2 acc = make_float2(0.f, 0.f);
    #pragma unroll 8
    for (int i = 0; i < 64; i++) {
        float2 wv = __ldg(&W[i * 64 + o]);
        float2 iv = ins[b * 64 + i];
        acc.x += iv.x * wv.x - iv.y * wv.y;
        acc.y += iv.x * wv.y + iv.y * wv.x;
    }
    outSpec[(size_t)jj * NM * 256 + (size_t)m * 256 + tid] = acc;
}

// precompute inverse: g_Ax[jj] += irfft(specB[jj])
__global__ __launch_bounds__(256) void k_invPre() {
    int img = blockIdx.x, jj = blockIdx.y, tid = threadIdx.x;
    const float2* spec = g_specB + (size_t)jj * NM * 2048;
    __shared__ float Zr[512], Zi[512];
    __shared__ __align__(16) float Gr[16 * 68];
    __shared__ __align__(16) float Gi[16 * 68];
    __shared__ float cs[64], ss[64];
    if (tid < 64) { cs[tid] = g_c[tid]; ss[tid] = g_s[tid]; }
    for (int idx = tid; idx < 512; idx += 256) {
        float2 v = spec[(size_t)idx * 2048 + img];
        Zr[idx] = v.x; Zi[idx] = v.y;
    }
    __syncthreads();
    {
        int ky = tid & 15, xg = tid >> 4, x0 = xg * 4;
        float gr[4] = {0,0,0,0}, gi[4] = {0,0,0,0};
        #pragma unroll 4
        for (int kxi = 0; kxi < 32; kxi++) {
            int kx = kxi + ((kxi >= 16) ? 32 : 0);
            float zr = Zr[kxi * 16 + ky], zi = Zi[kxi * 16 + ky];
            #pragma unroll
            for (int k = 0; k < 4; k++) {
                int id = (kx * (x0 + k)) & 63;
                float c = cs[id], s = ss[id];
                gr[k] += zr * c - zi * s;
                gi[k] += zr * s + zi * c;
            }
        }
        #pragma unroll
        for (int k = 0; k < 4; k++) { Gr[ky*68 + x0+k] = gr[k]; Gi[ky*68 + x0+k] = gi[k]; }
    }
    __syncthreads();
    {
        int y = tid & 63, xq = tid >> 6;
        float acc[16];
        #pragma unroll
        for (int q = 0; q < 16; q++) acc[q] = 0.f;
        for (int ky = 0; ky < 16; ky++) {
            int id = (ky * y) & 63;
            float c = cs[id], s = ss[id];
            const float4* a4 = (const float4*)(Gr + ky * 68 + xq * 16);
            const float4* b4 = (const float4*)(Gi + ky * 68 + xq * 16);
            #pragma unroll
            for (int q = 0; q < 4; q++) {
                float4 a = a4[q], b = b4[q];
                acc[q*4+0] += a.x * c - b.x * s;
                acc[q*4+1] += a.y * c - b.y * s;
                acc[q*4+2] += a.z * c - b.z * s;
                acc[q*4+3] += a.w * c - b.w * s;
            }
        }
        float* outp = g_Ax + (size_t)jj * 32 * 64 * HW + (size_t)img * HW;
        #pragma unroll
        for (int q = 0; q < 16; q++) {
            int off = (xq * 16 + q) * 64 + y;
            outp[off] += acc[q];
        }
    }
}

// Ax[jj][bt][o][p] = sum_i x[bt][i][p] * skw[2jj][i][o]   (4o x 4p blocking)
__global__ __launch_bounds__(256) void k_skipx(const float* __restrict__ x,
                                               const float* __restrict__ skw) {
    int p0 = blockIdx.x * 64, bt = blockIdx.y, jj = blockIdx.z, tid = threadIdx.x;
    __shared__ __align__(16) float xs[4096];
    __shared__ __align__(16) float ws[4096];
    {
        float4* xs4 = (float4*)xs;
        float4* ws4 = (float4*)ws;
        const float4* wsrc = (const float4*)(skw + (size_t)(2 * jj) * 4096);
        for (int idx = tid; idx < 1024; idx += 256) {
            int c = idx >> 4, v = idx & 15;
            xs4[idx] = *(const float4*)(x + (size_t)(bt * 64 + c) * HW + p0 + v * 4);
            ws4[idx] = wsrc[idx];
        }
    }
    __syncthreads();
    int pi = (tid & 15) * 4, o0 = (tid >> 4) * 4;
    float4 a[4];
    #pragma unroll
    for (int k = 0; k < 4; k++) a[k] = make_float4(0.f, 0.f, 0.f, 0.f);
    #pragma unroll 4
    for (int i = 0; i < 64; i++) {
        float4 xv = *(const float4*)(xs + i * 64 + pi);
        float4 wv = *(const float4*)(ws + i * 64 + o0);
        a[0].x += wv.x*xv.x; a[0].y += wv.x*xv.y; a[0].z += wv.x*xv.z; a[0].w += wv.x*xv.w;
        a[1].x += wv.y*xv.x; a[1].y += wv.y*xv.y; a[1].z += wv.y*xv.z; a[1].w += wv.y*xv.w;
        a[2].x += wv.z*xv.x; a[2].y += wv.z*xv.y; a[2].z += wv.z*xv.z; a[2].w += wv.z*xv.w;
        a[3].x += wv.w*xv.x; a[3].y += wv.w*xv.y; a[3].z += wv.w*xv.z; a[3].w += wv.w*xv.w;
    }
    #pragma unroll
    for (int oi = 0; oi < 4; oi++)
        *(float4*)(g_Ax + ((size_t)(jj * 32 + bt) * 64 + o0 + oi) * HW + p0 + pi) = a[oi];
}

// S13[w][b][o][p] = sum_i h[b][i][p] * skw[1 or 3][i][o]
__global__ __launch_bounds__(256) void k_hskip13(const float* __restrict__ skw) {
    int p0 = blockIdx.x * 64, b = blockIdx.y, tid = threadIdx.x;
    __shared__ __align__(16) float hs[4096];
    __shared__ __align__(16) float w1s[4096];
    __shared__ __align__(16) float w3s[4096];
    {
        float4* h4 = (float4*)hs;
        float4* a4 = (float4*)w1s;
        float4* b4 = (float4*)w3s;
        const float4* w1src = (const float4*)(skw + 4096);
        const float4* w3src = (const float4*)(skw + 3 * 4096);
        for (int idx = tid; idx < 1024; idx += 256) {
            int c = idx >> 4, v = idx & 15;
            h4[idx] = *(const float4*)(g_h + (size_t)(b * 64 + c) * HW + p0 + v * 4);
            a4[idx] = w1src[idx];
            b4[idx] = w3src[idx];
        }
    }
    __syncthreads();
    int pi = (tid & 15) * 4, o0 = (tid >> 4) * 4;
    float4 a1[4], a3[4];
    #pragma unroll
    for (int k = 0; k < 4; k++) { a1[k] = make_float4(0,0,0,0); a3[k] = make_float4(0,0,0,0); }
    #pragma unroll 2
    for (int i = 0; i < 64; i++) {
        float4 xv = *(const float4*)(hs + i * 64 + pi);
        float4 wa = *(const float4*)(w1s + i * 64 + o0);
        float4 wb = *(const float4*)(w3s + i * 64 + o0);
        a1[0].x += wa.x*xv.x; a1[0].y += wa.x*xv.y; a1[0].z += wa.x*xv.z; a1[0].w += wa.x*xv.w;
        a1[1].x += wa.y*xv.x; a1[1].y += wa.y*xv.y; a1[1].z += wa.y*xv.z; a1[1].w += wa.y*xv.w;
        a1[2].x += wa.z*xv.x; a1[2].y += wa.z*xv.y; a1[2].z += wa.z*xv.z; a1[2].w += wa.z*xv.w;
        a1[3].x += wa.w*xv.x; a1[3].y += wa.w*xv.y; a1[3].z += wa.w*xv.z; a1[3].w += wa.w*xv.w;
        a3[0].x += wb.x*xv.x; a3[0].y += wb.x*xv.y; a3[0].z += wb.x*xv.z; a3[0].w += wb.x*xv.w;
        a3[1].x += wb.y*xv.x; a3[1].y += wb.y*xv.y; a3[1].z += wb.y*xv.z; a3[1].w += wb.y*xv.w;
        a3[2].x += wb.z*xv.x; a3[2].y += wb.z*xv.y; a3[2].z += wb.z*xv.z; a3[2].w += wb.z*xv.w;
        a3[3].x += wb.w*xv.x; a3[3].y += wb.w*xv.y; a3[3].z += wb.w*xv.z; a3[3].w += wb.w*xv.w;
    }
    #pragma unroll
    for (int oi = 0; oi < 4; oi++) {
        *(float4*)(g_S13 + ((size_t)(0 * 4 + b) * 64 + o0 + oi) * HW + p0 + pi) = a1[oi];
        *(float4*)(g_S13 + ((size_t)(1 * 4 + b) * 64 + o0 + oi) * HW + p0 + pi) = a3[oi];
    }
}

// S5[b][o][p] = sum_i rh[b][i][p] * skw[5][i][o]
__global__ __launch_bounds__(256) void k_skip5(const float* __restrict__ skw) {
    int p0 = blockIdx.x * 64, b = blockIdx.y, tid = threadIdx.x;
    __shared__ __align__(16) float rs[4096];
    __shared__ __align__(16) float ws[4096];
    {
        float4* r4 = (float4*)rs;
        float4* w4 = (float4*)ws;
        const float4* wsrc = (const float4*)(skw + 5 * 4096);
        for (int idx = tid; idx < 1024; idx += 256) {
            int c = idx >> 4, v = idx & 15;
            r4[idx] = *(const float4*)(g_rh + (size_t)(b * 64 + c) * HW + p0 + v * 4);
            w4[idx] = wsrc[idx];
        }
    }
    __syncthreads();
    int pi = (tid & 15) * 4, o0 = (tid >> 4) * 4;
    float4 a[4];
    #pragma unroll
    for (int k = 0; k < 4; k++) a[k] = make_float4(0.f, 0.f, 0.f, 0.f);
    #pragma unroll 4
    for (int i = 0; i < 64; i++) {
        float4 xv = *(const float4*)(rs + i * 64 + pi);
        float4 wv = *(const float4*)(ws + i * 64 + o0);
        a[0].x += wv.x*xv.x; a[0].y += wv.x*xv.y; a[0].z += wv.x*xv.z; a[0].w += wv.x*xv.w;
        a[1].x += wv.y*xv.x; a[1].y += wv.y*xv.y; a[1].z += wv.y*xv.z; a[1].w += wv.y*xv.w;
        a[2].x += wv.z*xv.x; a[2].y += wv.z*xv.y; a[2].z += wv.z*xv.z; a[2].w += wv.z*xv.w;
        a[3].x += wv.w*xv.x; a[3].y += wv.w*xv.y; a[3].z += wv.w*xv.z; a[3].w += wv.w*xv.w;
    }
    #pragma unroll
    for (int oi = 0; oi < 4; oi++)
        *(float4*)(g_S5 + ((size_t)b * 64 + o0 + oi) * HW + p0 + pi) = a[oi];
}

// inverse DFT of z/r spectra + gate epilogue: z, rh = sigmoid(.)*h
__global__ __launch_bounds__(256) void k_invzr(const float* __restrict__ gb, int t) {
    int img = blockIdx.x, tid = threadIdx.x;
    int b = img >> 6, o = img & 63;
    __shared__ float Zr[2][512], Zi[2][512];
    __shared__ __align__(16) float Gr[2][16 * 68];
    __shared__ __align__(16) float Gi[2][16 * 68];
    __shared__ float cs[64], ss[64];
    if (tid < 64) { cs[tid] = g_c[tid]; ss[tid] = g_s[tid]; }
    #pragma unroll
    for (int jj = 0; jj < 2; jj++)
        for (int idx = tid; idx < 512; idx += 256) {
            float2 v = g_specF[(size_t)jj * NM * 256 + (size_t)idx * 256 + img];
            Zr[jj][idx] = v.x; Zi[jj][idx] = v.y;
        }
    __syncthreads();
    {
        int ky = tid & 15, xg = tid >> 4, x0 = xg * 4;
        #pragma unroll
        for (int jj = 0; jj < 2; jj++) {
            float gr[4] = {0,0,0,0}, gi[4] = {0,0,0,0};
            #pragma unroll 4
            for (int kxi = 0; kxi < 32; kxi++) {
                int kx = kxi + ((kxi >= 16) ? 32 : 0);
                float zr = Zr[jj][kxi * 16 + ky], zi = Zi[jj][kxi * 16 + ky];
                #pragma unroll
                for (int k = 0; k < 4; k++) {
                    int id = (kx * (x0 + k)) & 63;
                    float c = cs[id], s = ss[id];
                    gr[k] += zr * c - zi * s;
                    gi[k] += zr * s + zi * c;
                }
            }
            #pragma unroll
            for (int k = 0; k < 4; k++) { Gr[jj][ky*68 + x0+k] = gr[k]; Gi[jj][ky*68 + x0+k] = gi[k]; }
        }
    }
    __syncthreads();
    {
        int y = tid & 63, xq = tid >> 6;
        float a0[16], a1[16];
        #pragma unroll
        for (int q = 0; q < 16; q++) { a0[q] = 0.f; a1[q] = 0.f; }
        for (int ky = 0; ky < 16; ky++) {
            int id = (ky * y) & 63;
            float c = cs[id], s = ss[id];
            const float4* ar4 = (const float4*)(Gr[0] + ky * 68 + xq * 16);
            const float4* ai4 = (const float4*)(Gi[0] + ky * 68 + xq * 16);
            const float4* br4 = (const float4*)(Gr[1] + ky * 68 + xq * 16);
            const float4* bi4 = (const float4*)(Gi[1] + ky * 68 + xq * 16);
            #pragma unroll
            for (int q = 0; q < 4; q++) {
                float4 xr = ar4[q], xi = ai4[q];
                a0[q*4+0] += xr.x * c - xi.x * s;
                a0[q*4+1] += xr.y * c - xi.y * s;
                a0[q*4+2] += xr.z * c - xi.z * s;
                a0[q*4+3] += xr.w * c - xi.w * s;
                float4 yr = br4[q], yi = bi4[q];
                a1[q*4+0] += yr.x * c - yi.x * s;
                a1[q*4+1] += yr.y * c - yi.y * s;
                a1[q*4+2] += yr.z * c - yi.z * s;
                a1[q*4+3] += yr.w * c - yi.w * s;
            }
        }
        float gb0 = gb[0], gb1 = gb[1];
        int bt = b * 8 + t;
        const float* ax0 = g_Ax + ((size_t)(0 * 32 + bt) * 64 + o) * HW;
        const float* ax1 = g_Ax + ((size_t)(1 * 32 + bt) * 64 + o) * HW;
        const float* s1p = g_S13 + ((size_t)(0 * 4 + b) * 64 + o) * HW;
        const float* s3p = g_S13 + ((size_t)(1 * 4 + b) * 64 + o) * HW;
        const float* hp  = g_h + (size_t)img * HW;
        float* zp  = g_z + (size_t)img * HW;
        float* rhp = g_rh + (size_t)img * HW;
        #pragma unroll
        for (int q = 0; q < 16; q++) {
            int off = (xq * 16 + q) * 64 + y;
            float pre0 = a0[q] + ax0[off] + s1p[off] + gb0;
            float pre1 = a1[q] + ax1[off] + s3p[off] + gb1;
            float z = 1.f / (1.f + expf(-pre0));
            float r = 1.f / (1.f + expf(-pre1));
            zp[off] = z;
            rhp[off] = r * hp[off];
        }
    }
}

// inverse DFT of h_hat spectrum + selu + blend epilogue -> new h
__global__ __launch_bounds__(256) void k_inv5(const float* __restrict__ gb, int t) {
    int img = blockIdx.x, tid = threadIdx.x;
    int b = img >> 6, o = img & 63;
    __shared__ float Zr[512], Zi[512];
    __shared__ __align__(16) float Gr[16 * 68];
    __shared__ __align__(16) float Gi[16 * 68];
    __shared__ float cs[64], ss[64];
    if (tid < 64) { cs[tid] = g_c[tid]; ss[tid] = g_s[tid]; }
    for (int idx = tid; idx < 512; idx += 256) {
        float2 v = g_specF[(size_t)idx * 256 + img];
        Zr[idx] = v.x; Zi[idx] = v.y;
    }
    __syncthreads();
    {
        int ky = tid & 15, xg = tid >> 4, x0 = xg * 4;
        float gr[4] = {0,0,0,0}, gi[4] = {0,0,0,0};
        #pragma unroll 4
        for (int kxi = 0; kxi < 32; kxi++) {
            int kx = kxi + ((kxi >= 16) ? 32 : 0);
            float zr = Zr[kxi * 16 + ky], zi = Zi[kxi * 16 + ky];
            #pragma unroll
            for (int k = 0; k < 4; k++) {
                int id = (kx * (x0 + k)) & 63;
                float c = cs[id], s = ss[id];
                gr[k] += zr * c - zi * s;
                gi[k] += zr * s + zi * c;
            }
        }
        #pragma unroll
        for (int k = 0; k < 4; k++) { Gr[ky*68 + x0+k] = gr[k]; Gi[ky*68 + x0+k] = gi[k]; }
    }
    __syncthreads();
    {
        int y = tid & 63, xq = tid >> 6;
        float acc[16];
        #pragma unroll
        for (int q = 0; q < 16; q++) acc[q] = 0.f;
        for (int ky = 0; ky < 16; ky++) {
            int id = (ky * y) & 63;
            float c = cs[id], s = ss[id];
            const float4* a4 = (const float4*)(Gr + ky * 68 + xq * 16);
            const float4* b4 = (const float4*)(Gi + ky * 68 + xq * 16);
            #pragma unroll
            for (int q = 0; q < 4; q++) {
                float4 a = a4[q], bb = b4[q];
                acc[q*4+0] += a.x * c - bb.x * s;
                acc[q*4+1] += a.y * c - bb.y * s;
                acc[q*4+2] += a.z * c - bb.z * s;
                acc[q*4+3] += a.w * c - bb.w * s;
            }
        }
        float gb2 = gb[2];
        int bt = b * 8 + t;
        const float* ax2 = g_Ax + ((size_t)(2 * 32 + bt) * 64 + o) * HW;
        const float* s5p = g_S5 + ((size_t)b * 64 + o) * HW;
        const float* zp  = g_z + (size_t)img * HW;
        float* hp = g_h + (size_t)img * HW;
        const float SC = 1.0507009873554805f, AL = 1.6732632423543772f;
        #pragma unroll
        for (int q = 0; q < 16; q++) {
            int off = (xq * 16 + q) * 64 + y;
            float v = acc[q] + ax2[off] + s5p[off] + gb2;
            float hh = (v > 0.f) ? SC * v : SC * AL * (expf(v) - 1.f);
            float z = zp[off], h = hp[off];
            hp[off] = (1.f - z) * h + z * hh;
        }
    }
}

__global__ void k_copy(float* __restrict__ out) {
    int idx = blockIdx.x * 256 + threadIdx.x;
    out[idx] = g_h[idx];
}

extern "C" void kernel_launch(void* const* d_in, const int* in_sizes, int n_in,
                              void* d_out, int out_size) {
    const float* x   = (const float*)d_in[0];
    const float* sw1 = (const float*)d_in[1];
    const float* sw2 = (const float*)d_in[2];
    const float* skw = (const float*)d_in[3];
    const float* gb  = (const float*)d_in[4];
    const float* bh  = (const float*)d_in[5];
    float* out = (float*)d_out;

    float2 *pSpecX, *pSpecH, *pSpecF;
    float *pH, *pRH;
    cudaGetSymbolAddress((void**)&pSpecX, g_specX);
    cudaGetSymbolAddress((void**)&pSpecH, g_specH);
    cudaGetSymbolAddress((void**)&pSpecF, g_specF);
    cudaGetSymbolAddress((void**)&pH,  g_h);
    cudaGetSymbolAddress((void**)&pRH, g_rh);

    k_twiddle<<<1, 64>>>();
    k_wtrans<<<3072, 256>>>(sw1, sw2);
    k_hinit<<<4096, 256>>>(bh);
    k_skipx<<<dim3(64, 32, 3), 256>>>(x, skw);
    k_fwd<<<2048, 256>>>(x, pSpecX, 2048);
    k_mix32<<<dim3(512, 3), 256>>>();
    k_invPre<<<dim3(2048, 3), 256>>>();

    for (int t = 0; t < 8; t++) {
        k_hskip13<<<dim3(64, 4), 256>>>(skw);
        k_fwd<<<256, 256>>>(pH, pSpecH, 256);
        k_mix4<<<dim3(512, 2), 256>>>(pSpecH, pSpecF, 1, 3);
        k_invzr<<<256, 256>>>(gb, t);
        k_skip5<<<dim3(64, 4), 256>>>(skw);
        k_fwd<<<256, 256>>>(pRH, pSpecH, 256);
        k_mix4<<<dim3(512, 1), 256>>>(pSpecH, pSpecF, 5, 5);
        k_inv5<<<256, 256>>>(gb, t);
    }
    k_copy<<<4096, 256>>>(out);
}

// round 8
// speedup vs baseline: 1.2187x; 1.1111x over previous
#include <cuda_runtime.h>

#define HW 4096
#define NM 512

__device__ float  g_c[64], g_s[64];
__device__ float2 g_wmix[6 * NM * 4096];      // [j][m][i*64+o], scaled c_ky/4096
__device__ float2 g_specX[NM * 2048];         // [m][bt*64+c]
__device__ float2 g_specB[3 * NM * 2048];     // [jj][m][bt*64+o]
__device__ float2 g_specH[NM * 256];
__device__ float2 g_specF[2 * NM * 256];
__device__ float  g_Ax[3 * 32 * 64 * HW];     // [jj][bt][o][p]  (skip(x)+spectral(x))
__device__ float  g_S13[2 * 4 * 64 * HW];     // [w][b][o][p]  h-skips (skw1, skw3)
__device__ float  g_S5[4 * 64 * HW];          // rh-skip (skw5)
__device__ float  g_z[4 * 64 * HW];
__device__ float  g_rh[4 * 64 * HW];
__device__ float  g_h[4 * 64 * HW];

__global__ void k_twiddle() {
    int n = threadIdx.x;
    float s, c;
    sincospif(n * (1.0f / 32.0f), &s, &c);
    g_c[n] = c; g_s[n] = s;
}

// sw[j][i][o][kx][ky][2] -> g_wmix[j][m][i*64+o], m = kxi*16+ky
__global__ __launch_bounds__(256) void k_wtrans(const float* __restrict__ sw1,
                                                const float* __restrict__ sw2) {
    int bx = blockIdx.x;
    int j = bx >> 9, i = (bx >> 3) & 63, o0 = (bx & 7) * 8, tid = threadIdx.x;
    __shared__ float t1[4096], t2[4096];
    const float* s1 = sw1 + ((size_t)((j * 64 + i) * 64) + o0) * 512;
    const float* s2 = sw2 + ((size_t)((j * 64 + i) * 64) + o0) * 512;
    for (int idx = tid; idx < 4096; idx += 256) { t1[idx] = s1[idx]; t2[idx] = s2[idx]; }
    __syncthreads();
    float2* dst = g_wmix + (size_t)j * NM * 4096 + i * 64 + o0;
    for (int idx = tid; idx < NM * 8; idx += 256) {
        int m = idx >> 3, oo = idx & 7;
        int kxi = m >> 4, ky = m & 15;
        float f = (ky == 0 ? 1.0f : 2.0f) * (1.0f / 4096.0f);
        const float* tt = (kxi < 16) ? t1 : t2;
        int kk = (kxi < 16) ? kxi : (kxi - 16);
        float re = tt[oo * 512 + kk * 32 + ky * 2];
        float im = tt[oo * 512 + kk * 32 + ky * 2 + 1];
        dst[(size_t)m * 4096 + oo] = make_float2(re * f, im * f);
    }
}

__global__ void k_hinit(const float* __restrict__ bh) {
    float v = bh[0];
    int idx = blockIdx.x * 256 + threadIdx.x;
    g_h[idx] = v;
}

// partial forward DFT of one 64x64 image -> spec[m][img], m=kxi*16+ky
__global__ __launch_bounds__(256) void k_fwd(const float* __restrict__ in,
                                             float2* __restrict__ spec, int nimg) {
    __shared__ float xs[64 * 65];
    __shared__ float Yre[64 * 17], Yim[64 * 17];
    __shared__ float cs[64], ss[64];
    int tid = threadIdx.x, img = blockIdx.x;
    if (tid < 64) { cs[tid] = g_c[tid]; ss[tid] = g_s[tid]; }
    const float* src = in + (size_t)img * HW;
    for (int idx = tid; idx < HW; idx += 256)
        xs[(idx >> 6) * 65 + (idx & 63)] = src[idx];
    __syncthreads();
    {
        int x = tid >> 2, kq = tid & 3;
        const float* row = xs + x * 65;
        float ar[4] = {0,0,0,0}, ai[4] = {0,0,0,0};
        int ii[4] = {0,0,0,0};
        #pragma unroll 8
        for (int y = 0; y < 64; y++) {
            float v = row[y];
            #pragma unroll
            for (int k = 0; k < 4; k++) {
                ar[k] += v * cs[ii[k]];
                ai[k] -= v * ss[ii[k]];
                ii[k] = (ii[k] + kq * 4 + k) & 63;
            }
        }
        #pragma unroll
        for (int k = 0; k < 4; k++) { Yre[x*17 + kq*4+k] = ar[k]; Yim[x*17 + kq*4+k] = ai[k]; }
    }
    __syncthreads();
    {
        int ky = tid & 15, kg = tid >> 4;
        float z0r=0, z0i=0, z1r=0, z1i=0;
        int i0 = 0, i1 = 0;
        #pragma unroll 8
        for (int x = 0; x < 64; x++) {
            float yr = Yre[x*17 + ky], yi = Yim[x*17 + ky];
            float c = cs[i0], s = ss[i0];
            z0r += yr*c + yi*s; z0i += yi*c - yr*s;
            c = cs[i1]; s = ss[i1];
            z1r += yr*c + yi*s; z1i += yi*c - yr*s;
            i0 = (i0 + kg) & 63; i1 = (i1 + kg + 48) & 63;
        }
        spec[(size_t)(kg * 16 + ky) * nimg + img]        = make_float2(z0r, z0i);
        spec[(size_t)((kg + 16) * 16 + ky) * nimg + img] = make_float2(z1r, z1i);
    }
}

// mode mix, 32-image precompute
__global__ __launch_bounds__(256) void k_mix32() {
    int m = blockIdx.x, jj = blockIdx.y, tid = threadIdx.x;
    const float2* W = g_wmix + ((size_t)(2 * jj) * NM + m) * 4096;
    __shared__ float2 ins[2048];
    __shared__ float2 ws[4096];
    for (int idx = tid; idx < 2048; idx += 256) ins[idx] = g_specX[(size_t)m * 2048 + idx];
    for (int idx = tid; idx < 4096; idx += 256) ws[idx] = W[idx];
    __syncthreads();
    int o = tid & 63, bq = tid >> 6;
    float2 acc[8];
    #pragma unroll
    for (int g = 0; g < 8; g++) acc[g] = make_float2(0.f, 0.f);
    for (int i = 0; i < 64; i++) {
        float2 wv = ws[i * 64 + o];
        #pragma unroll
        for (int g = 0; g < 8; g++) {
            float2 iv = ins[(g * 4 + bq) * 64 + i];
            acc[g].x += iv.x * wv.x - iv.y * wv.y;
            acc[g].y += iv.x * wv.y + iv.y * wv.x;
        }
    }
    float2* outp = g_specB + (size_t)jj * NM * 2048 + (size_t)m * 2048;
    #pragma unroll
    for (int g = 0; g < 8; g++) outp[(g * 4 + bq) * 64 + o] = acc[g];
}

// mode mix for 4 images (in-loop)
__global__ __launch_bounds__(256) void k_mix4(const float2* __restrict__ inSpec,
                                              float2* __restrict__ outSpec,
                                              int wa, int wb) {
    int m = blockIdx.x, jj = blockIdx.y, tid = threadIdx.x;
    int w = jj ? wb : wa;
    const float2* W = g_wmix + ((size_t)w * NM + m) * 4096;
    __shared__ float2 ins[256];
    ins[tid] = inSpec[(size_t)m * 256 + tid];
    __syncthreads();
    int o = tid & 63, b = tid >> 6;
    float2 acc = make_float2(0.f, 0.f);
    #pragma unroll 8
    for (int i = 0; i < 64; i++) {
        float2 wv = __ldg(&W[i * 64 + o]);
        float2 iv = ins[b * 64 + i];
        acc.x += iv.x * wv.x - iv.y * wv.y;
        acc.y += iv.x * wv.y + iv.y * wv.x;
    }
    outSpec[(size_t)jj * NM * 256 + (size_t)m * 256 + tid] = acc;
}

// precompute inverse: g_Ax[jj] += irfft(specB[jj])
__global__ __launch_bounds__(256) void k_invPre() {
    int img = blockIdx.x, jj = blockIdx.y, tid = threadIdx.x;
    const float2* spec = g_specB + (size_t)jj * NM * 2048;
    __shared__ float Zr[512], Zi[512];
    __shared__ __align__(16) float Gr[16 * 68];
    __shared__ __align__(16) float Gi[16 * 68];
    __shared__ float cs[64], ss[64];
    if (tid < 64) { cs[tid] = g_c[tid]; ss[tid] = g_s[tid]; }
    for (int idx = tid; idx < 512; idx += 256) {
        float2 v = spec[(size_t)idx * 2048 + img];
        Zr[idx] = v.x; Zi[idx] = v.y;
    }
    __syncthreads();
    {
        int ky = tid & 15, xg = tid >> 4, x0 = xg * 4;
        float gr[4] = {0,0,0,0}, gi[4] = {0,0,0,0};
        #pragma unroll 4
        for (int kxi = 0; kxi < 32; kxi++) {
            int kx = kxi + ((kxi >= 16) ? 32 : 0);
            float zr = Zr[kxi * 16 + ky], zi = Zi[kxi * 16 + ky];
            #pragma unroll
            for (int k = 0; k < 4; k++) {
                int id = (kx * (x0 + k)) & 63;
                float c = cs[id], s = ss[id];
                gr[k] += zr * c - zi * s;
                gi[k] += zr * s + zi * c;
            }
        }
        #pragma unroll
        for (int k = 0; k < 4; k++) { Gr[ky*68 + x0+k] = gr[k]; Gi[ky*68 + x0+k] = gi[k]; }
    }
    __syncthreads();
    {
        int y = tid & 63, xq = tid >> 6;
        float acc[16];
        #pragma unroll
        for (int q = 0; q < 16; q++) acc[q] = 0.f;
        for (int ky = 0; ky < 16; ky++) {
            int id = (ky * y) & 63;
            float c = cs[id], s = ss[id];
            const float4* a4 = (const float4*)(Gr + ky * 68 + xq * 16);
            const float4* b4 = (const float4*)(Gi + ky * 68 + xq * 16);
            #pragma unroll
            for (int q = 0; q < 4; q++) {
                float4 a = a4[q], b = b4[q];
                acc[q*4+0] += a.x * c - b.x * s;
                acc[q*4+1] += a.y * c - b.y * s;
                acc[q*4+2] += a.z * c - b.z * s;
                acc[q*4+3] += a.w * c - b.w * s;
            }
        }
        float* outp = g_Ax + (size_t)jj * 32 * 64 * HW + (size_t)img * HW;
        #pragma unroll
        for (int q = 0; q < 16; q++) {
            int off = (xq * 16 + q) * 64 + y;
            outp[off] += acc[q];
        }
    }
}

// Ax[jj][bt][o][p] = sum_i x[bt][i][p] * skw[2jj][i][o]
__global__ __launch_bounds__(256) void k_skipx(const float* __restrict__ x,
                                               const float* __restrict__ skw) {
    int p0 = blockIdx.x * 64, bt = blockIdx.y, jj = blockIdx.z, tid = threadIdx.x;
    __shared__ __align__(16) float xs[4096];
    __shared__ __align__(16) float ws[4096];
    {
        float4* xs4 = (float4*)xs;
        float4* ws4 = (float4*)ws;
        const float4* wsrc = (const float4*)(skw + (size_t)(2 * jj) * 4096);
        for (int idx = tid; idx < 1024; idx += 256) {
            int c = idx >> 4, v = idx & 15;
            xs4[idx] = *(const float4*)(x + (size_t)(bt * 64 + c) * HW + p0 + v * 4);
            ws4[idx] = wsrc[idx];
        }
    }
    __syncthreads();
    int pi = (tid & 15) * 4, o0 = (tid >> 4) * 4;
    float4 a[4];
    #pragma unroll
    for (int k = 0; k < 4; k++) a[k] = make_float4(0.f, 0.f, 0.f, 0.f);
    #pragma unroll 4
    for (int i = 0; i < 64; i++) {
        float4 xv = *(const float4*)(xs + i * 64 + pi);
        float4 wv = *(const float4*)(ws + i * 64 + o0);
        a[0].x += wv.x*xv.x; a[0].y += wv.x*xv.y; a[0].z += wv.x*xv.z; a[0].w += wv.x*xv.w;
        a[1].x += wv.y*xv.x; a[1].y += wv.y*xv.y; a[1].z += wv.y*xv.z; a[1].w += wv.y*xv.w;
        a[2].x += wv.z*xv.x; a[2].y += wv.z*xv.y; a[2].z += wv.z*xv.z; a[2].w += wv.z*xv.w;
        a[3].x += wv.w*xv.x; a[3].y += wv.w*xv.y; a[3].z += wv.w*xv.z; a[3].w += wv.w*xv.w;
    }
    #pragma unroll
    for (int oi = 0; oi < 4; oi++)
        *(float4*)(g_Ax + ((size_t)(jj * 32 + bt) * 64 + o0 + oi) * HW + p0 + pi) = a[oi];
}

// S13[w][b][o][p] = sum_i h[b][i][p] * skw[1 or 3][i][o]
__global__ __launch_bounds__(256) void k_hskip13(const float* __restrict__ skw) {
    int p0 = blockIdx.x * 64, b = blockIdx.y, tid = threadIdx.x;
    __shared__ __align__(16) float hs[4096];
    __shared__ __align__(16) float w1s[4096];
    __shared__ __align__(16) float w3s[4096];
    {
        float4* h4 = (float4*)hs;
        float4* a4 = (float4*)w1s;
        float4* b4 = (float4*)w3s;
        const float4* w1src = (const float4*)(skw + 4096);
        const float4* w3src = (const float4*)(skw + 3 * 4096);
        for (int idx = tid; idx < 1024; idx += 256) {
            int c = idx >> 4, v = idx & 15;
            h4[idx] = *(const float4*)(g_h + (size_t)(b * 64 + c) * HW + p0 + v * 4);
            a4[idx] = w1src[idx];
            b4[idx] = w3src[idx];
        }
    }
    __syncthreads();
    int pi = (tid & 15) * 4, o0 = (tid >> 4) * 4;
    float4 a1[4], a3[4];
    #pragma unroll
    for (int k = 0; k < 4; k++) { a1[k] = make_float4(0,0,0,0); a3[k] = make_float4(0,0,0,0); }
    #pragma unroll 2
    for (int i = 0; i < 64; i++) {
        float4 xv = *(const float4*)(hs + i * 64 + pi);
        float4 wa = *(const float4*)(w1s + i * 64 + o0);
        float4 wb = *(const float4*)(w3s + i * 64 + o0);
        a1[0].x += wa.x*xv.x; a1[0].y += wa.x*xv.y; a1[0].z += wa.x*xv.z; a1[0].w += wa.x*xv.w;
        a1[1].x += wa.y*xv.x; a1[1].y += wa.y*xv.y; a1[1].z += wa.y*xv.z; a1[1].w += wa.y*xv.w;
        a1[2].x += wa.z*xv.x; a1[2].y += wa.z*xv.y; a1[2].z += wa.z*xv.z; a1[2].w += wa.z*xv.w;
        a1[3].x += wa.w*xv.x; a1[3].y += wa.w*xv.y; a1[3].z += wa.w*xv.z; a1[3].w += wa.w*xv.w;
        a3[0].x += wb.x*xv.x; a3[0].y += wb.x*xv.y; a3[0].z += wb.x*xv.z; a3[0].w += wb.x*xv.w;
        a3[1].x += wb.y*xv.x; a3[1].y += wb.y*xv.y; a3[1].z += wb.y*xv.z; a3[1].w += wb.y*xv.w;
        a3[2].x += wb.z*xv.x; a3[2].y += wb.z*xv.y; a3[2].z += wb.z*xv.z; a3[2].w += wb.z*xv.w;
        a3[3].x += wb.w*xv.x; a3[3].y += wb.w*xv.y; a3[3].z += wb.w*xv.z; a3[3].w += wb.w*xv.w;
    }
    #pragma unroll
    for (int oi = 0; oi < 4; oi++) {
        *(float4*)(g_S13 + ((size_t)(0 * 4 + b) * 64 + o0 + oi) * HW + p0 + pi) = a1[oi];
        *(float4*)(g_S13 + ((size_t)(1 * 4 + b) * 64 + o0 + oi) * HW + p0 + pi) = a3[oi];
    }
}

// S5[b][o][p] = sum_i rh[b][i][p] * skw[5][i][o]
__global__ __launch_bounds__(256) void k_skip5(const float* __restrict__ skw) {
    int p0 = blockIdx.x * 64, b = blockIdx.y, tid = threadIdx.x;
    __shared__ __align__(16) float rs[4096];
    __shared__ __align__(16) float ws[4096];
    {
        float4* r4 = (float4*)rs;
        float4* w4 = (float4*)ws;
        const float4* wsrc = (const float4*)(skw + 5 * 4096);
        for (int idx = tid; idx < 1024; idx += 256) {
            int c = idx >> 4, v = idx & 15;
            r4[idx] = *(const float4*)(g_rh + (size_t)(b * 64 + c) * HW + p0 + v * 4);
            w4[idx] = wsrc[idx];
        }
    }
    __syncthreads();
    int pi = (tid & 15) * 4, o0 = (tid >> 4) * 4;
    float4 a[4];
    #pragma unroll
    for (int k = 0; k < 4; k++) a[k] = make_float4(0.f, 0.f, 0.f, 0.f);
    #pragma unroll 4
    for (int i = 0; i < 64; i++) {
        float4 xv = *(const float4*)(rs + i * 64 + pi);
        float4 wv = *(const float4*)(ws + i * 64 + o0);
        a[0].x += wv.x*xv.x; a[0].y += wv.x*xv.y; a[0].z += wv.x*xv.z; a[0].w += wv.x*xv.w;
        a[1].x += wv.y*xv.x; a[1].y += wv.y*xv.y; a[1].z += wv.y*xv.z; a[1].w += wv.y*xv.w;
        a[2].x += wv.z*xv.x; a[2].y += wv.z*xv.y; a[2].z += wv.z*xv.z; a[2].w += wv.z*xv.w;
        a[3].x += wv.w*xv.x; a[3].y += wv.w*xv.y; a[3].z += wv.w*xv.z; a[3].w += wv.w*xv.w;
    }
    #pragma unroll
    for (int oi = 0; oi < 4; oi++)
        *(float4*)(g_S5 + ((size_t)b * 64 + o0 + oi) * HW + p0 + pi) = a[oi];
}

// inverse DFT of z/r spectra + gate epilogue + FUSED forward DFT of rh
__global__ __launch_bounds__(256) void k_invzrF(const float* __restrict__ gb, int t) {
    int img = blockIdx.x, tid = threadIdx.x;
    int b = img >> 6, o = img & 63;
    __shared__ float Zr[2][512], Zi[2][512];
    __shared__ __align__(16) float Gr[2][16 * 68];
    __shared__ __align__(16) float Gi[2][16 * 68];
    __shared__ float xs[64 * 65];
    __shared__ float cs[64], ss[64];
    if (tid < 64) { cs[tid] = g_c[tid]; ss[tid] = g_s[tid]; }
    #pragma unroll
    for (int jj = 0; jj < 2; jj++)
        for (int idx = tid; idx < 512; idx += 256) {
            float2 v = g_specF[(size_t)jj * NM * 256 + (size_t)idx * 256 + img];
            Zr[jj][idx] = v.x; Zi[jj][idx] = v.y;
        }
    __syncthreads();
    {
        int ky = tid & 15, xg = tid >> 4, x0 = xg * 4;
        #pragma unroll
        for (int jj = 0; jj < 2; jj++) {
            float gr[4] = {0,0,0,0}, gi[4] = {0,0,0,0};
            #pragma unroll 4
            for (int kxi = 0; kxi < 32; kxi++) {
                int kx = kxi + ((kxi >= 16) ? 32 : 0);
                float zr = Zr[jj][kxi * 16 + ky], zi = Zi[jj][kxi * 16 + ky];
                #pragma unroll
                for (int k = 0; k < 4; k++) {
                    int id = (kx * (x0 + k)) & 63;
                    float c = cs[id], s = ss[id];
                    gr[k] += zr * c - zi * s;
                    gi[k] += zr * s + zi * c;
                }
            }
            #pragma unroll
            for (int k = 0; k < 4; k++) { Gr[jj][ky*68 + x0+k] = gr[k]; Gi[jj][ky*68 + x0+k] = gi[k]; }
        }
    }
    __syncthreads();
    {
        int y = tid & 63, xq = tid >> 6;
        float a0[16], a1[16];
        #pragma unroll
        for (int q = 0; q < 16; q++) { a0[q] = 0.f; a1[q] = 0.f; }
        for (int ky = 0; ky < 16; ky++) {
            int id = (ky * y) & 63;
            float c = cs[id], s = ss[id];
            const float4* ar4 = (const float4*)(Gr[0] + ky * 68 + xq * 16);
            const float4* ai4 = (const float4*)(Gi[0] + ky * 68 + xq * 16);
            const float4* br4 = (const float4*)(Gr[1] + ky * 68 + xq * 16);
            const float4* bi4 = (const float4*)(Gi[1] + ky * 68 + xq * 16);
            #pragma unroll
            for (int q = 0; q < 4; q++) {
                float4 xr = ar4[q], xi = ai4[q];
                a0[q*4+0] += xr.x * c - xi.x * s;
                a0[q*4+1] += xr.y * c - xi.y * s;
                a0[q*4+2] += xr.z * c - xi.z * s;
                a0[q*4+3] += xr.w * c - xi.w * s;
                float4 yr = br4[q], yi = bi4[q];
                a1[q*4+0] += yr.x * c - yi.x * s;
                a1[q*4+1] += yr.y * c - yi.y * s;
                a1[q*4+2] += yr.z * c - yi.z * s;
                a1[q*4+3] += yr.w * c - yi.w * s;
            }
        }
        float gb0 = gb[0], gb1 = gb[1];
        int bt = b * 8 + t;
        const float* ax0 = g_Ax + ((size_t)(0 * 32 + bt) * 64 + o) * HW;
        const float* ax1 = g_Ax + ((size_t)(1 * 32 + bt) * 64 + o) * HW;
        const float* s1p = g_S13 + ((size_t)(0 * 4 + b) * 64 + o) * HW;
        const float* s3p = g_S13 + ((size_t)(1 * 4 + b) * 64 + o) * HW;
        const float* hp  = g_h + (size_t)img * HW;
        float* zp  = g_z + (size_t)img * HW;
        float* rhp = g_rh + (size_t)img * HW;
        #pragma unroll
        for (int q = 0; q < 16; q++) {
            int x = xq * 16 + q;
            int off = x * 64 + y;
            float pre0 = a0[q] + ax0[off] + s1p[off] + gb0;
            float pre1 = a1[q] + ax1[off] + s3p[off] + gb1;
            float z = 1.f / (1.f + expf(-pre0));
            float r = 1.f / (1.f + expf(-pre1));
            float rh = r * hp[off];
            zp[off]  = z;
            rhp[off] = rh;
            xs[x * 65 + y] = rh;
        }
    }
    __syncthreads();
    // fused forward DFT of rh (Y buffers alias dead Gr[0]/Gi[0]: both 1088 floats)
    float* Yre = Gr[0];
    float* Yim = Gi[0];
    {
        int x = tid >> 2, kq = tid & 3;
        const float* row = xs + x * 65;
        float ar[4] = {0,0,0,0}, ai[4] = {0,0,0,0};
        int ii[4] = {0,0,0,0};
        #pragma unroll 8
        for (int y = 0; y < 64; y++) {
            float v = row[y];
            #pragma unroll
            for (int k = 0; k < 4; k++) {
                ar[k] += v * cs[ii[k]];
                ai[k] -= v * ss[ii[k]];
                ii[k] = (ii[k] + kq * 4 + k) & 63;
            }
        }
        #pragma unroll
        for (int k = 0; k < 4; k++) { Yre[x*17 + kq*4+k] = ar[k]; Yim[x*17 + kq*4+k] = ai[k]; }
    }
    __syncthreads();
    {
        int ky = tid & 15, kg = tid >> 4;
        float z0r=0, z0i=0, z1r=0, z1i=0;
        int i0 = 0, i1 = 0;
        #pragma unroll 8
        for (int x = 0; x < 64; x++) {
            float yr = Yre[x*17 + ky], yi = Yim[x*17 + ky];
            float c = cs[i0], s = ss[i0];
            z0r += yr*c + yi*s; z0i += yi*c - yr*s;
            c = cs[i1]; s = ss[i1];
            z1r += yr*c + yi*s; z1i += yi*c - yr*s;
            i0 = (i0 + kg) & 63; i1 = (i1 + kg + 48) & 63;
        }
        g_specH[(size_t)(kg * 16 + ky) * 256 + img]        = make_float2(z0r, z0i);
        g_specH[(size_t)((kg + 16) * 16 + ky) * 256 + img] = make_float2(z1r, z1i);
    }
}

// inverse DFT of h_hat + selu + blend -> new h, FUSED forward DFT of new h
__global__ __launch_bounds__(256) void k_inv5F(const float* __restrict__ gb, int t) {
    int img = blockIdx.x, tid = threadIdx.x;
    int b = img >> 6, o = img & 63;
    __shared__ float Zr[512], Zi[512];
    __shared__ __align__(16) float Gr[16 * 68];
    __shared__ __align__(16) float Gi[16 * 68];
    __shared__ float xs[64 * 65];
    __shared__ float cs[64], ss[64];
    if (tid < 64) { cs[tid] = g_c[tid]; ss[tid] = g_s[tid]; }
    for (int idx = tid; idx < 512; idx += 256) {
        float2 v = g_specF[(size_t)idx * 256 + img];
        Zr[idx] = v.x; Zi[idx] = v.y;
    }
    __syncthreads();
    {
        int ky = tid & 15, xg = tid >> 4, x0 = xg * 4;
        float gr[4] = {0,0,0,0}, gi[4] = {0,0,0,0};
        #pragma unroll 4
        for (int kxi = 0; kxi < 32; kxi++) {
            int kx = kxi + ((kxi >= 16) ? 32 : 0);
            float zr = Zr[kxi * 16 + ky], zi = Zi[kxi * 16 + ky];
            #pragma unroll
            for (int k = 0; k < 4; k++) {
                int id = (kx * (x0 + k)) & 63;
                float c = cs[id], s = ss[id];
                gr[k] += zr * c - zi * s;
                gi[k] += zr * s + zi * c;
            }
        }
        #pragma unroll
        for (int k = 0; k < 4; k++) { Gr[ky*68 + x0+k] = gr[k]; Gi[ky*68 + x0+k] = gi[k]; }
    }
    __syncthreads();
    {
        int y = tid & 63, xq = tid >> 6;
        float acc[16];
        #pragma unroll
        for (int q = 0; q < 16; q++) acc[q] = 0.f;
        for (int ky = 0; ky < 16; ky++) {
            int id = (ky * y) & 63;
            float c = cs[id], s = ss[id];
            const float4* a4 = (const float4*)(Gr + ky * 68 + xq * 16);
            const float4* b4 = (const float4*)(Gi + ky * 68 + xq * 16);
            #pragma unroll
            for (int q = 0; q < 4; q++) {
                float4 a = a4[q], bb = b4[q];
                acc[q*4+0] += a.x * c - bb.x * s;
                acc[q*4+1] += a.y * c - bb.y * s;
                acc[q*4+2] += a.z * c - bb.z * s;
                acc[q*4+3] += a.w * c - bb.w * s;
            }
        }
        float gb2 = gb[2];
        int bt = b * 8 + t;
        const float* ax2 = g_Ax + ((size_t)(2 * 32 + bt) * 64 + o) * HW;
        const float* s5p = g_S5 + ((size_t)b * 64 + o) * HW;
        const float* zp  = g_z + (size_t)img * HW;
        float* hp = g_h + (size_t)img * HW;
        const float SC = 1.0507009873554805f, AL = 1.6732632423543772f;
        #pragma unroll
        for (int q = 0; q < 16; q++) {
            int x = xq * 16 + q;
            int off = x * 64 + y;
            float v = acc[q] + ax2[off] + s5p[off] + gb2;
            float hh = (v > 0.f) ? SC * v : SC * AL * (expf(v) - 1.f);
            float z = zp[off], h = hp[off];
            float hn = (1.f - z) * h + z * hh;
            hp[off] = hn;
            xs[x * 65 + y] = hn;
        }
    }
    __syncthreads();
    // fused forward DFT of new h (Y aliases dead Gr/Gi: 1088 floats each)
    float* Yre = Gr;
    float* Yim = Gi;
    {
        int x = tid >> 2, kq = tid & 3;
        const float* row = xs + x * 65;
        float ar[4] = {0,0,0,0}, ai[4] = {0,0,0,0};
        int ii[4] = {0,0,0,0};
        #pragma unroll 8
        for (int y = 0; y < 64; y++) {
            float v = row[y];
            #pragma unroll
            for (int k = 0; k < 4; k++) {
                ar[k] += v * cs[ii[k]];
                ai[k] -= v * ss[ii[k]];
                ii[k] = (ii[k] + kq * 4 + k) & 63;
            }
        }
        #pragma unroll
        for (int k = 0; k < 4; k++) { Yre[x*17 + kq*4+k] = ar[k]; Yim[x*17 + kq*4+k] = ai[k]; }
    }
    __syncthreads();
    {
        int ky = tid & 15, kg = tid >> 4;
        float z0r=0, z0i=0, z1r=0, z1i=0;
        int i0 = 0, i1 = 0;
        #pragma unroll 8
        for (int x = 0; x < 64; x++) {
            float yr = Yre[x*17 + ky], yi = Yim[x*17 + ky];
            float c = cs[i0], s = ss[i0];
            z0r += yr*c + yi*s; z0i += yi*c - yr*s;
            c = cs[i1]; s = ss[i1];
            z1r += yr*c + yi*s; z1i += yi*c - yr*s;
            i0 = (i0 + kg) & 63; i1 = (i1 + kg + 48) & 63;
        }
        g_specH[(size_t)(kg * 16 + ky) * 256 + img]        = make_float2(z0r, z0i);
        g_specH[(size_t)((kg + 16) * 16 + ky) * 256 + img] = make_float2(z1r, z1i);
    }
}

__global__ void k_copy(float* __restrict__ out) {
    int idx = blockIdx.x * 256 + threadIdx.x;
    out[idx] = g_h[idx];
}

extern "C" void kernel_launch(void* const* d_in, const int* in_sizes, int n_in,
                              void* d_out, int out_size) {
    const float* x   = (const float*)d_in[0];
    const float* sw1 = (const float*)d_in[1];
    const float* sw2 = (const float*)d_in[2];
    const float* skw = (const float*)d_in[3];
    const float* gb  = (const float*)d_in[4];
    const float* bh  = (const float*)d_in[5];
    float* out = (float*)d_out;

    float2 *pSpecX, *pSpecH, *pSpecF;
    float *pH;
    cudaGetSymbolAddress((void**)&pSpecX, g_specX);
    cudaGetSymbolAddress((void**)&pSpecH, g_specH);
    cudaGetSymbolAddress((void**)&pSpecF, g_specF);
    cudaGetSymbolAddress((void**)&pH, g_h);

    k_twiddle<<<1, 64>>>();
    k_wtrans<<<3072, 256>>>(sw1, sw2);
    k_hinit<<<4096, 256>>>(bh);
    k_skipx<<<dim3(64, 32, 3), 256>>>(x, skw);
    k_fwd<<<2048, 256>>>(x, pSpecX, 2048);
    k_mix32<<<dim3(512, 3), 256>>>();
    k_invPre<<<dim3(2048, 3), 256>>>();

    // prologue for recurrence: spectra + h-skips of h0
    k_hskip13<<<dim3(64, 4), 256>>>(skw);
    k_fwd<<<256, 256>>>(pH, pSpecH, 256);

    for (int t = 0; t < 8; t++) {
        k_mix4<<<dim3(512, 2), 256>>>(pSpecH, pSpecF, 1, 3);
        k_invzrF<<<256, 256>>>(gb, t);          // z, rh, specH(rh)
        k_skip5<<<dim3(64, 4), 256>>>(skw);
        k_mix4<<<dim3(512, 1), 256>>>(pSpecH, pSpecF, 5, 5);
        k_inv5F<<<256, 256>>>(gb, t);           // new h, specH(h')
        if (t < 7) k_hskip13<<<dim3(64, 4), 256>>>(skw);
    }
    k_copy<<<4096, 256>>>(out);
}